// round 15
// baseline (speedup 1.0000x reference)
#include <cuda_runtime.h>
#include <cuda_fp16.h>
#include <cstdint>

#define N        8192
#define D        192
#define BM       128
#define NB       64
#define NTILES   2080             // NB*(NB+1)/2
#define TILE_BYTES (BM * D * 2)   // 49152
#define NCTA     148              // 1 CTA/SM, 512 threads (all co-resident)
#define QW       14               // 2080 = 148*14 + 8
#define REMW     8
#define CHUNKS   128              // phase-1: 64 rows per CTA

// ---------------- device globals (zero-initialized at load) ----------------
__device__ double g_loss;
__device__ float  g_colacc[8][D];
__device__ float  g_sqacc[8];
__device__ int    g_pcount;
__device__ int    g_ready;
__device__ int    g_mcount;
__device__ float  g_sq[N];
__device__ float  g_c2;                 // log2(e)/(16*bw)
__device__ uint4  g_xh[N * D * 2 / 16]; // fp16 x, row stride 384B, 16B-group XOR swizzle

// ---------------- helpers ----------------
__device__ __forceinline__ uint32_t smem_u32(const void* p) {
    uint32_t a;
    asm("{ .reg .u64 t; cvta.to.shared.u64 t, %1; cvt.u32.u64 %0, t; }" : "=r"(a) : "l"(p));
    return a;
}
#define MBAR_INIT(a, c) asm volatile("mbarrier.init.shared.b64 [%0], %1;" :: "r"(a), "r"(c) : "memory")
#define MBAR_EXPECT_TX(a, b) asm volatile("mbarrier.arrive.expect_tx.shared.b64 _, [%0], %1;" :: "r"(a), "r"(b) : "memory")
#define MBAR_WAIT(a, ph) do { \
    uint32_t _m = (a), _p = (ph), _d; \
    asm volatile("{ .reg .pred p; mbarrier.try_wait.parity.acquire.cta.shared::cta.b64 p, [%1], %2; selp.b32 %0,1,0,p; }" \
        : "=r"(_d) : "r"(_m), "r"(_p) : "memory"); \
    if (!_d) { asm volatile("{ .reg .pred P1; WL_%=: mbarrier.try_wait.parity.acquire.cta.shared::cta.b64 P1, [%0], %1, 0x989680; @P1 bra.uni WD_%=; bra.uni WL_%=; WD_%=: }" \
        :: "r"(_m), "r"(_p) : "memory"); } } while (0)
__device__ __forceinline__ void bulk_g2s(uint32_t dst, const void* src, uint32_t bytes, uint32_t mbar) {
    asm volatile("cp.async.bulk.shared::cluster.global.mbarrier::complete_tx::bytes [%0], [%1], %2, [%3];"
        :: "r"(dst), "l"(src), "r"(bytes), "r"(mbar) : "memory");
}
#define LDSM_X4(r0, r1, r2, r3, a) \
    asm volatile("ldmatrix.sync.aligned.m8n8.x4.shared.b16 {%0,%1,%2,%3}, [%4];" \
        : "=r"(r0), "=r"(r1), "=r"(r2), "=r"(r3) : "r"(a))
#define MMA16816H(d, a, b0, b1) \
    asm volatile("mma.sync.aligned.m16n8k16.row.col.f16.f16.f16.f16 " \
        "{%0,%1},{%2,%3,%4,%5},{%6,%7},{%0,%1};" \
        : "+r"((d)[0]), "+r"((d)[1]) \
        : "r"((a)[0]), "r"((a)[1]), "r"((a)[2]), "r"((a)[3]), "r"(b0), "r"(b1))
__device__ __forceinline__ float ex2f(float x) {
    float r; asm("ex2.approx.ftz.f32 %0, %1;" : "=f"(r) : "f"(x)); return r;
}
// named barriers (512 = whole CTA, mixed arrive/sync; 256 = producers only)
#define NBAR_SYNC(id)   asm volatile("bar.sync %0, 512;"   :: "r"(id) : "memory")
#define NBAR_ARRIVE(id) asm volatile("bar.arrive %0, 512;" :: "r"(id) : "memory")
#define PBAR_SYNC()     asm volatile("bar.sync 6, 256;"    ::: "memory")
#define FENCE_CTA()     asm volatile("membar.cta;" ::: "memory")
#define STS_V2(addr, r0, r1) \
    asm volatile("st.shared.v2.u32 [%0], {%1,%2};" :: "r"(addr), "r"(r0), "r"(r1) : "memory")
#define LDS_V2(r0, r1, addr) \
    asm volatile("ld.shared.v2.u32 {%0,%1}, [%2];" : "=r"(r0), "=r"(r1) : "r"(addr))

// producer: load one k-step's fragments into buffer S (4 A x4 + 2 B x4)
#define LDF(S, KG) do { \
    uint32_t _ga = (((uint32_t)(2*(KG)) + ahi) ^ swz) << 4; \
    uint32_t _gb = (((uint32_t)(2*(KG)) + bhi) ^ swz) << 4; \
    LDSM_X4(fa[S][0][0],fa[S][0][1],fa[S][0][2],fa[S][0][3], baseA + _ga); \
    LDSM_X4(fa[S][1][0],fa[S][1][1],fa[S][1][2],fa[S][1][3], baseA + 6144u + _ga); \
    LDSM_X4(fa[S][2][0],fa[S][2][1],fa[S][2][2],fa[S][2][3], baseA + 12288u + _ga); \
    LDSM_X4(fa[S][3][0],fa[S][3][1],fa[S][3][2],fa[S][3][3], baseA + 18432u + _ga); \
    LDSM_X4(fb[S][0][0],fb[S][0][1],fb[S][0][2],fb[S][0][3], baseB + _gb); \
    LDSM_X4(fb[S][1][0],fb[S][1][1],fb[S][1][2],fb[S][1][3], baseB + 6144u + _gb); \
} while (0)
#define MMAF(S) do { \
    _Pragma("unroll") \
    for (int _fm = 0; _fm < 4; _fm++) { \
        MMA16816H(acc[_fm][0], fa[S][_fm], fb[S][0][0], fb[S][0][1]); \
        MMA16816H(acc[_fm][1], fa[S][_fm], fb[S][0][2], fb[S][0][3]); \
        MMA16816H(acc[_fm][2], fa[S][_fm], fb[S][1][0], fb[S][1][1]); \
        MMA16816H(acc[_fm][3], fa[S][_fm], fb[S][1][2], fb[S][1][3]); \
    } \
} while (0)

// consumer: epilogue of one loaded dot pair (4 elements) into parity buckets
#define EPID(LO, HI, NI0, NI1, NJ0, NJ1) do { \
    float2 _p0 = __half22float2(*(half2*)&(LO)); \
    float2 _p1 = __half22float2(*(half2*)&(HI)); \
    float _t, _t2, _t4, _t8; \
    _t = ex2f(fmaf(_p0.x, tc2, (NI0)+(NJ0))); _t2=_t*_t; _t4=_t2*_t2; _t8=_t4*_t4; \
    ta0 += (fmaf(_t,_t,_t) + fmaf(_t4,_t4,_t4)) + _t8*_t8; \
    _t = ex2f(fmaf(_p0.y, tc2, (NI0)+(NJ1))); _t2=_t*_t; _t4=_t2*_t2; _t8=_t4*_t4; \
    ta1 += (fmaf(_t,_t,_t) + fmaf(_t4,_t4,_t4)) + _t8*_t8; \
    _t = ex2f(fmaf(_p1.x, tc2, (NI1)+(NJ0))); _t2=_t*_t; _t4=_t2*_t2; _t8=_t4*_t4; \
    ta0 += (fmaf(_t,_t,_t) + fmaf(_t4,_t4,_t4)) + _t8*_t8; \
    _t = ex2f(fmaf(_p1.y, tc2, (NI1)+(NJ1))); _t2=_t*_t; _t4=_t2*_t2; _t8=_t4*_t4; \
    ta1 += (fmaf(_t,_t,_t) + fmaf(_t4,_t4,_t4)) + _t8*_t8; \
} while (0)

// ---------------- smem layout ----------------
#define OFF_A    0
#define OFF_B    49152
#define OFF_DOT  98304          // 2 x 32768 (double-buffered fp16 dot dumps)
#define OFF_MBAR 163840
#define OFF_RED  163856         // 16 floats
#define SMEM_DYN (163840 + 128 + 1024)

__global__ __launch_bounds__(512, 1) void k_all(const float* __restrict__ x,
                                                float* __restrict__ out) {
    extern __shared__ char dsm[];
    uint32_t sb = (smem_u32(dsm) + 1023u) & ~1023u;
    char* sp = dsm + (sb - smem_u32(dsm));

    int tid  = threadIdx.x;
    int wid  = tid >> 5, lane = tid & 31;
    int c    = blockIdx.x;

    __shared__ int s_go, s_win;

    // ================= phase 1: convert + reductions (CTAs 0..127, 64 rows) ========
    if (c < CHUNKS) {
        float* s_stage = (float*)sp;                 // [64][192] (48KB)
        float* s_sq    = (float*)(sp + 49152);       // [64][24]
        float* s_rowsq = (float*)(sp + 55296);       // [64]

        #pragma unroll
        for (int it = 0; it < 3; it++) {
            int idx = tid + it * 512;                // 0..1535
            int r = idx / 24, g = idx % 24;
            int gr = c * 64 + r;
            const float* src = x + (size_t)gr * D + g * 8;
            float4 f0 = *(const float4*)src;
            float4 f1 = *(const float4*)(src + 4);

            half2 hh[4];
            hh[0] = __float22half2_rn(make_float2(f0.x, f0.y));
            hh[1] = __float22half2_rn(make_float2(f0.z, f0.w));
            hh[2] = __float22half2_rn(make_float2(f1.x, f1.y));
            hh[3] = __float22half2_rn(make_float2(f1.z, f1.w));
            *(uint4*)((char*)g_xh + (size_t)gr * 384 +
                      (((uint32_t)g ^ (uint32_t)(gr & 7)) << 4)) = *(uint4*)hh;

            s_sq[r * 24 + g] = f0.x * f0.x + f0.y * f0.y + f0.z * f0.z + f0.w * f0.w
                             + f1.x * f1.x + f1.y * f1.y + f1.z * f1.z + f1.w * f1.w;
            float* sxp = &s_stage[r * D + g * 8];
            sxp[0] = f0.x; sxp[1] = f0.y; sxp[2] = f0.z; sxp[3] = f0.w;
            sxp[4] = f1.x; sxp[5] = f1.y; sxp[6] = f1.z; sxp[7] = f1.w;
        }
        __syncthreads();

        if (tid < 64) {
            float v = 0.f;
            #pragma unroll
            for (int k = 0; k < 24; k++) v += s_sq[tid * 24 + k];
            g_sq[c * 64 + tid] = v;
            s_rowsq[tid] = v;
        }
        if (tid >= 64 && tid < 64 + D) {
            int col = tid - 64;
            float cs = 0.f;
            #pragma unroll
            for (int r = 0; r < 64; r++) cs += s_stage[r * D + col];
            atomicAdd(&g_colacc[c & 7][col], cs);
        }
        __syncthreads();
        if (tid == 0) {
            float tot = 0.f;
            #pragma unroll
            for (int r = 0; r < 64; r++) tot += s_rowsq[r];
            atomicAdd(&g_sqacc[c & 7], tot);
        }
    }

    // ================= grid barrier + bandwidth constant =================
    __threadfence();
    __syncthreads();
    if (tid == 0) s_go = (atomicAdd(&g_pcount, 1) == NCTA - 1) ? 1 : 0;
    __syncthreads();
    if (s_go) {
        __threadfence();
        float* s_red2 = (float*)sp;
        float cs = 0.f;
        if (tid < D) {
            #pragma unroll
            for (int r = 0; r < 8; r++) cs += __ldcg(&g_colacc[r][tid]);
        }
        if (tid < 256) s_red2[tid] = cs * cs;
        __syncthreads();
        if (tid < 128) s_red2[tid] += s_red2[tid + 128];
        __syncthreads();
        if (tid < 64) s_red2[tid] += s_red2[tid + 64];
        __syncthreads();
        if (tid < 32) {
            float v = s_red2[tid] + s_red2[tid + 32];
            #pragma unroll
            for (int o = 16; o > 0; o >>= 1) v += __shfl_down_sync(0xffffffffu, v, o);
            if (tid == 0) {
                float sumsq = 0.f;
                #pragma unroll
                for (int r = 0; r < 8; r++) sumsq += __ldcg(&g_sqacc[r]);
                double sumL2 = 2.0 * (double)N * (double)sumsq - 2.0 * (double)v;
                double bw = sumL2 / ((double)N * (double)N - (double)N);
                bw *= 0.25;
                g_c2 = (float)(1.4426950408889634 / (bw * 16.0));
                g_loss = 0.0;
                __threadfence();
                atomicExch(&g_ready, 1);
            }
        }
    }
    if (tid == 0) {
        volatile int* rp = &g_ready;
        while (*rp == 0) {}
    }
    __syncthreads();
    __threadfence();

    // ================= phase 2: warp-specialized tile loop =================
    int start = (c < REMW) ? c * (QW + 1) : REMW * (QW + 1) + (c - REMW) * QW;
    int count = (c < REMW) ? QW + 1 : QW;
    int bi = 0, s = start;
    while (s >= NB - bi) { s -= NB - bi; bi++; }
    int bj = bi + s;

    uint32_t mbar = sb + OFF_MBAR;
    if (tid == 0) MBAR_INIT(mbar, 1);
    __syncthreads();
    if (tid == 0) {
        MBAR_EXPECT_TX(mbar, 2 * TILE_BYTES);
        const char* xh = (const char*)g_xh;
        bulk_g2s(sb + OFF_A, xh + (size_t)bi * TILE_BYTES, TILE_BYTES, mbar);
        bulk_g2s(sb + OFF_B, xh + (size_t)bj * TILE_BYTES, TILE_BYTES, mbar);
    }

    float c2 = __ldcg(&g_c2), tc2 = 2.f * c2, nc2 = -c2;

    if (wid < 8) {
        // ======================= PRODUCERS (warps 0..7) =======================
        int e  = wid;
        int wM = e >> 2, wN = e & 3;
        uint32_t swz   = (uint32_t)(lane & 7);
        uint32_t ahi   = (uint32_t)(lane >> 4);
        uint32_t bhi   = (uint32_t)((lane >> 3) & 1);
        uint32_t baseA = sb + OFF_A + (uint32_t)(wM * 64 + (lane & 15)) * 384u;
        uint32_t baseB = sb + OFF_B + (uint32_t)(wN * 32 + ((lane >> 4) << 3) + (lane & 7)) * 384u;
        uint32_t dbase = sb + OFF_DOT + (uint32_t)e * 4096u + (uint32_t)lane * 8u;

        int phase = 0;
        for (int k = 0; k < count; k++) {
            MBAR_WAIT(mbar, phase);
            phase ^= 1;

            uint32_t acc[4][4][2];
            #pragma unroll
            for (int i = 0; i < 4; i++)
                #pragma unroll
                for (int j = 0; j < 4; j++) { acc[i][j][0] = 0u; acc[i][j][1] = 0u; }

            uint32_t fa[2][4][4], fb[2][2][4];
            LDF(0, 0);
            LDF(1, 1);  MMAF(0);
            LDF(0, 2);  MMAF(1);
            LDF(1, 3);  MMAF(0);
            LDF(0, 4);  MMAF(1);
            LDF(1, 5);  MMAF(0);
            LDF(0, 6);  MMAF(1);
            LDF(1, 7);  MMAF(0);
            LDF(0, 8);  MMAF(1);
            LDF(1, 9);  MMAF(0);
            LDF(0, 10); MMAF(1);
            LDF(1, 11); MMAF(0);
            MMAF(1);

            PBAR_SYNC();            // all producers done reading A/B
            int nbi = bi, nbj = bj + 1;
            if (nbj == NB) { nbi = bi + 1; nbj = nbi; }
            if (k + 1 < count && tid == 0) {
                uint32_t bytes = TILE_BYTES + ((nbi != bi) ? TILE_BYTES : 0);
                MBAR_EXPECT_TX(mbar, bytes);
                const char* xh = (const char*)g_xh;
                if (nbi != bi)
                    bulk_g2s(sb + OFF_A, xh + (size_t)nbi * TILE_BYTES, TILE_BYTES, mbar);
                bulk_g2s(sb + OFF_B, xh + (size_t)nbj * TILE_BYTES, TILE_BYTES, mbar);
            }

            if (k >= 2) NBAR_SYNC(4 + (k & 1));      // wait dot buffer free
            uint32_t daddr = dbase + (uint32_t)(k & 1) * 32768u;
            #pragma unroll
            for (int fm = 0; fm < 4; fm++)
                #pragma unroll
                for (int fn = 0; fn < 4; fn++)
                    STS_V2(daddr + (uint32_t)(fm * 4 + fn) * 256u,
                           acc[fm][fn][0], acc[fm][fn][1]);
            FENCE_CTA();
            NBAR_ARRIVE(2 + (k & 1));                // dots ready

            bi = nbi; bj = nbj;
        }
        // producers contribute zero to the reduction
        float* s_red = (float*)(sp + OFF_RED);
        if (lane == 0) s_red[wid] = 0.f;
    } else {
        // ======================= CONSUMERS (warps 8..15) =======================
        int e  = wid - 8;
        int wM = e >> 2, wN = e & 3;
        int gID = lane >> 2, tig = lane & 3;
        uint32_t dbase = sb + OFF_DOT + (uint32_t)e * 4096u + (uint32_t)lane * 8u;

        float master = 0.f;
        for (int k = 0; k < count; k++) {
            bool diag = (bi == bj);
            float nsi[8], nsj[8];
            #pragma unroll
            for (int fm = 0; fm < 4; fm++) {
                nsi[fm * 2]     = nc2 * __ldg(&g_sq[bi * BM + wM * 64 + fm * 16 + gID]);
                nsi[fm * 2 + 1] = nc2 * __ldg(&g_sq[bi * BM + wM * 64 + fm * 16 + gID + 8]);
            }
            #pragma unroll
            for (int fn = 0; fn < 4; fn++) {
                nsj[fn * 2]     = nc2 * __ldg(&g_sq[bj * BM + wN * 32 + fn * 8 + tig * 2]);
                nsj[fn * 2 + 1] = nc2 * __ldg(&g_sq[bj * BM + wN * 32 + fn * 8 + tig * 2 + 1]);
            }

            NBAR_SYNC(2 + (k & 1));                  // wait dots
            uint32_t daddr = dbase + (uint32_t)(k & 1) * 32768u;

            float ta0 = 0.f, ta1 = 0.f;
            #pragma unroll
            for (int fm = 0; fm < 4; fm++)
                #pragma unroll
                for (int fn = 0; fn < 4; fn++) {
                    uint32_t d0, d1;
                    LDS_V2(d0, d1, daddr + (uint32_t)(fm * 4 + fn) * 256u);
                    EPID(d0, d1, nsi[fm * 2], nsi[fm * 2 + 1], nsj[fn * 2], nsj[fn * 2 + 1]);
                }
            NBAR_ARRIVE(4 + (k & 1));                // buffer free

            float tp = (gID & 1) ? (ta1 - ta0) : (ta0 - ta1);
            master += diag ? tp : 2.f * tp;          // diag self-counts (+own diag ~ +5N)

            int nbj = bj + 1;
            if (nbj == NB) { bi = bi + 1; bj = bi; }
            else bj = nbj;
        }

        #pragma unroll
        for (int o = 16; o > 0; o >>= 1) master += __shfl_xor_sync(0xffffffffu, master, o);
        float* s_red = (float*)(sp + OFF_RED);
        if (lane == 0) s_red[wid] = master;
    }

    __syncthreads();
    if (tid == 0) {
        float* s_red = (float*)(sp + OFF_RED);
        float v = 0.f;
        #pragma unroll
        for (int w = 8; w < 16; w++) v += s_red[w];
        atomicAdd(&g_loss, (double)v);
    }

    // ================= finalization by last CTA (parallel state reset) =================
    __threadfence();
    __syncthreads();
    if (tid == 0) s_win = (atomicAdd(&g_mcount, 1) == NCTA - 1) ? 1 : 0;
    __syncthreads();
    if (s_win) {
        __threadfence();
        if (tid < D) {
            #pragma unroll
            for (int r = 0; r < 8; r++) g_colacc[r][tid] = 0.f;
        }
        if (tid < 8) g_sqacc[tid] = 0.f;
        __syncthreads();
        if (tid == 0) {
            double hn = (double)(N / 2);
            out[0] = (float)(g_loss / (hn * hn));   // diag tiles already include ~5N
            g_pcount = 0;
            g_ready  = 0;
            g_mcount = 0;
        }
    }
}

// ---------------- launch ----------------
extern "C" void kernel_launch(void* const* d_in, const int* in_sizes, int n_in,
                              void* d_out, int out_size) {
    const float* x = (const float*)d_in[0];
    float* out = (float*)d_out;

    cudaFuncSetAttribute(k_all, cudaFuncAttributeMaxDynamicSharedMemorySize, SMEM_DYN);
    k_all<<<NCTA, 512, SMEM_DYN>>>(x, out);
}

// round 16
// speedup vs baseline: 1.1134x; 1.1134x over previous
#include <cuda_runtime.h>
#include <cuda_fp16.h>
#include <cstdint>

#define N        8192
#define D        192
#define BM       128
#define NB       64
#define NTILES   2080             // NB*(NB+1)/2
#define TILE_BYTES (BM * D * 2)   // 49152
#define NCTA     296              // 148 SM x 2 (all co-resident: barrier-safe)
#define CHUNKS   256              // 8192 rows / 32

// ---------------- device globals ----------------
__device__ double g_loss;
__device__ float  g_colacc[8][D];
__device__ float  g_sqacc[8];
__device__ int    g_pcount;
__device__ int    g_ready;
__device__ int    g_mcount;
__device__ int    g_tile = NCTA;        // dynamic tile counter (reset each run)
__device__ float  g_sq[N];
__device__ float  g_c2;                 // log2(e)/(16*bw)
__device__ uint4  g_xh[N * D * 2 / 16]; // fp16 x, row stride 384B, 16B-group XOR swizzle

// ---------------- helpers ----------------
__device__ __forceinline__ uint32_t smem_u32(const void* p) {
    uint32_t a;
    asm("{ .reg .u64 t; cvta.to.shared.u64 t, %1; cvt.u32.u64 %0, t; }" : "=r"(a) : "l"(p));
    return a;
}
#define MBAR_INIT(a, c) asm volatile("mbarrier.init.shared.b64 [%0], %1;" :: "r"(a), "r"(c) : "memory")
#define MBAR_EXPECT_TX(a, b) asm volatile("mbarrier.arrive.expect_tx.shared.b64 _, [%0], %1;" :: "r"(a), "r"(b) : "memory")
#define MBAR_WAIT(a, ph) do { \
    uint32_t _m = (a), _p = (ph), _d; \
    asm volatile("{ .reg .pred p; mbarrier.try_wait.parity.acquire.cta.shared::cta.b64 p, [%1], %2; selp.b32 %0,1,0,p; }" \
        : "=r"(_d) : "r"(_m), "r"(_p) : "memory"); \
    if (!_d) { asm volatile("{ .reg .pred P1; WL_%=: mbarrier.try_wait.parity.acquire.cta.shared::cta.b64 P1, [%0], %1, 0x989680; @P1 bra.uni WD_%=; bra.uni WL_%=; WD_%=: }" \
        :: "r"(_m), "r"(_p) : "memory"); } } while (0)
__device__ __forceinline__ void bulk_g2s(uint32_t dst, const void* src, uint32_t bytes, uint32_t mbar) {
    asm volatile("cp.async.bulk.shared::cluster.global.mbarrier::complete_tx::bytes [%0], [%1], %2, [%3];"
        :: "r"(dst), "l"(src), "r"(bytes), "r"(mbar) : "memory");
}
#define LDSM_X4(r0, r1, r2, r3, a) \
    asm volatile("ldmatrix.sync.aligned.m8n8.x4.shared.b16 {%0,%1,%2,%3}, [%4];" \
        : "=r"(r0), "=r"(r1), "=r"(r2), "=r"(r3) : "r"(a))
#define MMA16816H(d, a, b0, b1) \
    asm volatile("mma.sync.aligned.m16n8k16.row.col.f16.f16.f16.f16 " \
        "{%0,%1},{%2,%3,%4,%5},{%6,%7},{%0,%1};" \
        : "+r"((d)[0]), "+r"((d)[1]) \
        : "r"((a)[0]), "r"((a)[1]), "r"((a)[2]), "r"((a)[3]), "r"(b0), "r"(b1))
__device__ __forceinline__ float ex2f(float x) {
    float r; asm("ex2.approx.ftz.f32 %0, %1;" : "=f"(r) : "f"(x)); return r;
}

// triangular decode: tile t -> (bi, bj), bj >= bi
__device__ __forceinline__ void tdecode(int t, int& bi, int& bj) {
    float s = (2.0f * NB + 1.0f);
    int r = (int)((s - sqrtf(s * s - 8.0f * (float)t)) * 0.5f);
    if (r < 0) r = 0;
    if (r > NB - 1) r = NB - 1;
    while (r > 0 && r * NB - r * (r - 1) / 2 > t) r--;
    while ((r + 1) * NB - (r + 1) * r / 2 <= t) r++;
    bi = r;
    bj = r + (t - (r * NB - r * (r - 1) / 2));
}

// load one k-step's fragments into buffer S: 4 A x4 (64 rows) + 2 B x4 (32 cols)
#define LDF(S, KG) do { \
    uint32_t _ga = (((uint32_t)(2*(KG)) + ahi) ^ swz) << 4; \
    uint32_t _gb = (((uint32_t)(2*(KG)) + bhi) ^ swz) << 4; \
    LDSM_X4(fa[S][0][0],fa[S][0][1],fa[S][0][2],fa[S][0][3], baseA + _ga); \
    LDSM_X4(fa[S][1][0],fa[S][1][1],fa[S][1][2],fa[S][1][3], baseA + 6144u + _ga); \
    LDSM_X4(fa[S][2][0],fa[S][2][1],fa[S][2][2],fa[S][2][3], baseA + 12288u + _ga); \
    LDSM_X4(fa[S][3][0],fa[S][3][1],fa[S][3][2],fa[S][3][3], baseA + 18432u + _ga); \
    LDSM_X4(fb[S][0][0],fb[S][0][1],fb[S][0][2],fb[S][0][3], baseB + _gb); \
    LDSM_X4(fb[S][1][0],fb[S][1][1],fb[S][1][2],fb[S][1][3], baseB + 6144u + _gb); \
} while (0)
#define MMAF(S) do { \
    _Pragma("unroll") \
    for (int _fm = 0; _fm < 4; _fm++) { \
        MMA16816H(acc[_fm][0], fa[S][_fm], fb[S][0][0], fb[S][0][1]); \
        MMA16816H(acc[_fm][1], fa[S][_fm], fb[S][0][2], fb[S][0][3]); \
        MMA16816H(acc[_fm][2], fa[S][_fm], fb[S][1][0], fb[S][1][1]); \
        MMA16816H(acc[_fm][3], fa[S][_fm], fb[S][1][2], fb[S][1][3]); \
    } \
} while (0)

// epilogue of one acc pair (4 elements) into parity buckets ta0/ta1
#define EPIA(FM, FN) do { \
    float2 _p0 = __half22float2(*(half2*)&acc[FM][FN][0]); \
    float2 _p1 = __half22float2(*(half2*)&acc[FM][FN][1]); \
    float _t, _t2, _t4, _t8; \
    _t = ex2f(fmaf(_p0.x, tc2, nsi[(FM)*2]   + nsj[(FN)*2]));   _t2=_t*_t; _t4=_t2*_t2; _t8=_t4*_t4; \
    ta0 += (fmaf(_t,_t,_t) + fmaf(_t4,_t4,_t4)) + _t8*_t8; \
    _t = ex2f(fmaf(_p0.y, tc2, nsi[(FM)*2]   + nsj[(FN)*2+1])); _t2=_t*_t; _t4=_t2*_t2; _t8=_t4*_t4; \
    ta1 += (fmaf(_t,_t,_t) + fmaf(_t4,_t4,_t4)) + _t8*_t8; \
    _t = ex2f(fmaf(_p1.x, tc2, nsi[(FM)*2+1] + nsj[(FN)*2]));   _t2=_t*_t; _t4=_t2*_t2; _t8=_t4*_t4; \
    ta0 += (fmaf(_t,_t,_t) + fmaf(_t4,_t4,_t4)) + _t8*_t8; \
    _t = ex2f(fmaf(_p1.y, tc2, nsi[(FM)*2+1] + nsj[(FN)*2+1])); _t2=_t*_t; _t4=_t2*_t2; _t8=_t4*_t4; \
    ta1 += (fmaf(_t,_t,_t) + fmaf(_t4,_t4,_t4)) + _t8*_t8; \
} while (0)

// ---------------- fused persistent kernel ----------------
#define OFF_A    0
#define OFF_B    49152
#define OFF_MBAR 98304
#define OFF_RED  98320
#define SMEM_DYN (98304 + 64 + 1024)

__global__ __launch_bounds__(256, 2) void k_all(const float* __restrict__ x,
                                                float* __restrict__ out) {
    extern __shared__ char dsm[];
    uint32_t sb = (smem_u32(dsm) + 1023u) & ~1023u;
    char* sp = dsm + (sb - smem_u32(dsm));

    int tid  = threadIdx.x;
    int wid  = tid >> 5, lane = tid & 31;
    int wM   = wid >> 2, wN = wid & 3;
    int gID  = lane >> 2, tig = lane & 3;
    int c    = blockIdx.x;

    __shared__ int s_go, s_win;
    __shared__ int s_next[2];

    // ================= phase 1: convert + reductions (CTAs 0..255) =================
    if (c < CHUNKS) {
        float* s_stage = (float*)sp;
        float* s_sq    = (float*)(sp + 24576);
        float* s_rowsq = (float*)(sp + 27648);

        #pragma unroll
        for (int it = 0; it < 3; it++) {
            int idx = tid + it * 256;
            int r = idx / 24, g = idx % 24;
            int gr = c * 32 + r;
            const float* src = x + (size_t)gr * D + g * 8;
            float4 f0 = *(const float4*)src;
            float4 f1 = *(const float4*)(src + 4);

            half2 hh[4];
            hh[0] = __float22half2_rn(make_float2(f0.x, f0.y));
            hh[1] = __float22half2_rn(make_float2(f0.z, f0.w));
            hh[2] = __float22half2_rn(make_float2(f1.x, f1.y));
            hh[3] = __float22half2_rn(make_float2(f1.z, f1.w));
            *(uint4*)((char*)g_xh + (size_t)gr * 384 +
                      (((uint32_t)g ^ (uint32_t)(gr & 7)) << 4)) = *(uint4*)hh;

            s_sq[r * 24 + g] = f0.x * f0.x + f0.y * f0.y + f0.z * f0.z + f0.w * f0.w
                             + f1.x * f1.x + f1.y * f1.y + f1.z * f1.z + f1.w * f1.w;
            float* sxp = &s_stage[r * D + g * 8];
            sxp[0] = f0.x; sxp[1] = f0.y; sxp[2] = f0.z; sxp[3] = f0.w;
            sxp[4] = f1.x; sxp[5] = f1.y; sxp[6] = f1.z; sxp[7] = f1.w;
        }
        __syncthreads();

        if (tid < 32) {
            float v = 0.f;
            #pragma unroll
            for (int k = 0; k < 24; k++) v += s_sq[tid * 24 + k];
            g_sq[c * 32 + tid] = v;
            s_rowsq[tid] = v;
        }
        if (tid >= 64) {
            int col = tid - 64;
            float cs = 0.f;
            #pragma unroll
            for (int r = 0; r < 32; r++) cs += s_stage[r * D + col];
            atomicAdd(&g_colacc[c & 7][col], cs);
        }
        __syncthreads();
        if (tid == 0) {
            float tot = 0.f;
            #pragma unroll
            for (int r = 0; r < 32; r++) tot += s_rowsq[r];
            atomicAdd(&g_sqacc[c & 7], tot);
        }
    }

    // ================= grid barrier + bandwidth constant =================
    __threadfence();
    __syncthreads();
    if (tid == 0) s_go = (atomicAdd(&g_pcount, 1) == NCTA - 1) ? 1 : 0;
    __syncthreads();
    if (s_go) {
        __threadfence();
        float* s_red2 = (float*)sp;
        float cs = 0.f;
        if (tid < D) {
            #pragma unroll
            for (int r = 0; r < 8; r++) cs += __ldcg(&g_colacc[r][tid]);
        }
        s_red2[tid] = cs * cs;
        __syncthreads();
        #pragma unroll
        for (int o = 128; o >= 32; o >>= 1) {
            if (tid < o) s_red2[tid] += s_red2[tid + o];
            __syncthreads();
        }
        if (tid < 32) {
            float v = s_red2[tid];
            #pragma unroll
            for (int o = 16; o > 0; o >>= 1) v += __shfl_down_sync(0xffffffffu, v, o);
            if (tid == 0) {
                float sumsq = 0.f;
                #pragma unroll
                for (int r = 0; r < 8; r++) sumsq += __ldcg(&g_sqacc[r]);
                double sumL2 = 2.0 * (double)N * (double)sumsq - 2.0 * (double)v;
                double bw = sumL2 / ((double)N * (double)N - (double)N);
                bw *= 0.25;
                g_c2 = (float)(1.4426950408889634 / (bw * 16.0));
                g_loss = 0.0;
                __threadfence();
                atomicExch(&g_ready, 1);
            }
        }
    }
    if (tid == 0) {
        volatile int* rp = &g_ready;
        while (*rp == 0) {}
    }
    __syncthreads();
    __threadfence();

    // ================= phase 2: dynamically scheduled HMMA tile loop =================
    int t = c;                    // first tile = own block id (g_tile starts at NCTA)
    int bi, bj;
    tdecode(t, bi, bj);

    uint32_t mbar = sb + OFF_MBAR;
    if (tid == 0) MBAR_INIT(mbar, 1);
    __syncthreads();
    if (tid == 0) {
        MBAR_EXPECT_TX(mbar, 2 * TILE_BYTES);
        const char* xh = (const char*)g_xh;
        bulk_g2s(sb + OFF_A, xh + (size_t)bi * TILE_BYTES, TILE_BYTES, mbar);
        bulk_g2s(sb + OFF_B, xh + (size_t)bj * TILE_BYTES, TILE_BYTES, mbar);
    }

    uint32_t swz   = (uint32_t)(lane & 7);
    uint32_t ahi   = (uint32_t)(lane >> 4);
    uint32_t bhi   = (uint32_t)((lane >> 3) & 1);
    uint32_t baseA = sb + OFF_A + (uint32_t)(wM * 64 + (lane & 15)) * 384u;
    uint32_t baseB = sb + OFF_B + (uint32_t)(wN * 32 + ((lane >> 4) << 3) + (lane & 7)) * 384u;

    float c2 = __ldcg(&g_c2), tc2 = 2.f * c2, nc2 = -c2;

    float master = 0.f;
    int phase = 0;
    int it = 0;

    while (t < NTILES) {
        // grab next tile early (ATOMG latency hides under mbar wait + MMA)
        if (tid == 0) s_next[it & 1] = atomicAdd(&g_tile, 1);

        bool diag = (bi == bj);
        float nsi[8], nsj[8];
        #pragma unroll
        for (int fm = 0; fm < 4; fm++) {
            nsi[fm * 2]     = nc2 * __ldg(&g_sq[bi * BM + wM * 64 + fm * 16 + gID]);
            nsi[fm * 2 + 1] = nc2 * __ldg(&g_sq[bi * BM + wM * 64 + fm * 16 + gID + 8]);
        }
        #pragma unroll
        for (int fn = 0; fn < 4; fn++) {
            nsj[fn * 2]     = nc2 * __ldg(&g_sq[bj * BM + wN * 32 + fn * 8 + tig * 2]);
            nsj[fn * 2 + 1] = nc2 * __ldg(&g_sq[bj * BM + wN * 32 + fn * 8 + tig * 2 + 1]);
        }

        MBAR_WAIT(mbar, phase);
        phase ^= 1;

        uint32_t acc[4][4][2];
        #pragma unroll
        for (int i = 0; i < 4; i++)
            #pragma unroll
            for (int j = 0; j < 4; j++) { acc[i][j][0] = 0u; acc[i][j][1] = 0u; }

        // software-pipelined mainloop: load kg+1 before issuing kg's MMAs
        uint32_t fa[2][4][4], fb[2][2][4];
        LDF(0, 0);
        LDF(1, 1);  MMAF(0);
        LDF(0, 2);  MMAF(1);
        LDF(1, 3);  MMAF(0);
        LDF(0, 4);  MMAF(1);
        LDF(1, 5);  MMAF(0);
        LDF(0, 6);  MMAF(1);
        LDF(1, 7);  MMAF(0);
        LDF(0, 8);  MMAF(1);
        LDF(1, 9);  MMAF(0);
        LDF(0, 10); MMAF(1);
        LDF(1, 11); MMAF(0);
        MMAF(1);

        __syncthreads();   // smem reads done (and s_next visible) -> safe to overwrite

        int nt = s_next[it & 1];
        int nbi = 0, nbj = 0;
        if (nt < NTILES) {
            tdecode(nt, nbi, nbj);
            if (tid == 0) {
                MBAR_EXPECT_TX(mbar, 2 * TILE_BYTES);
                const char* xh = (const char*)g_xh;
                bulk_g2s(sb + OFF_A, xh + (size_t)nbi * TILE_BYTES, TILE_BYTES, mbar);
                bulk_g2s(sb + OFF_B, xh + (size_t)nbj * TILE_BYTES, TILE_BYTES, mbar);
            }
        }

        // ---- epilogue (registers only; overlaps async prefetch) ----
        float ta0 = 0.f, ta1 = 0.f;
        EPIA(0,0); EPIA(0,1); EPIA(0,2); EPIA(0,3);
        EPIA(1,0); EPIA(1,1); EPIA(1,2); EPIA(1,3);
        EPIA(2,0); EPIA(2,1); EPIA(2,2); EPIA(2,3);
        EPIA(3,0); EPIA(3,1); EPIA(3,2); EPIA(3,3);

        // diag tiles self-count both orderings (+own diagonal -> replaces +5N), weight 1
        float tp = (gID & 1) ? (ta1 - ta0) : (ta0 - ta1);
        master += diag ? tp : 2.f * tp;

        t = nt; bi = nbi; bj = nbj;
        it++;
    }

    float part = master;
    #pragma unroll
    for (int o = 16; o > 0; o >>= 1) part += __shfl_xor_sync(0xffffffffu, part, o);
    float* s_red = (float*)(sp + OFF_RED);
    if (lane == 0) s_red[wid] = part;
    __syncthreads();
    if (tid == 0) {
        float v = 0.f;
        #pragma unroll
        for (int w = 0; w < 8; w++) v += s_red[w];
        atomicAdd(&g_loss, (double)v);
    }

    // ================= finalization by last CTA (parallel state reset) =================
    __threadfence();
    __syncthreads();
    if (tid == 0) s_win = (atomicAdd(&g_mcount, 1) == NCTA - 1) ? 1 : 0;
    __syncthreads();
    if (s_win) {
        __threadfence();
        if (tid < D) {
            #pragma unroll
            for (int r = 0; r < 8; r++) g_colacc[r][tid] = 0.f;
        }
        if (tid < 8) g_sqacc[tid] = 0.f;
        __syncthreads();
        if (tid == 0) {
            double hn = (double)(N / 2);
            out[0] = (float)(g_loss / (hn * hn));   // diag tiles already include ~5N
            g_pcount = 0;
            g_ready  = 0;
            g_mcount = 0;
            g_tile   = NCTA;
        }
    }
}

// ---------------- launch ----------------
extern "C" void kernel_launch(void* const* d_in, const int* in_sizes, int n_in,
                              void* d_out, int out_size) {
    const float* x = (const float*)d_in[0];
    float* out = (float*)d_out;

    cudaFuncSetAttribute(k_all, cudaFuncAttributeMaxDynamicSharedMemorySize, SMEM_DYN);
    k_all<<<NCTA, 256, SMEM_DYN>>>(x, out);
}

// round 17
// speedup vs baseline: 1.1287x; 1.0137x over previous
#include <cuda_runtime.h>
#include <cuda_fp16.h>
#include <cstdint>

#define N        8192
#define D        192
#define BM       128
#define NB       64
#define NTILES   2080             // NB*(NB+1)/2
#define TILE_BYTES (BM * D * 2)   // 49152
#define NCTA     296              // 148 SM x 2 (all co-resident: barrier-safe)
#define CHUNKS   256              // 8192 rows / 32

// ---------------- device globals ----------------
__device__ double g_loss;
__device__ float  g_colacc[8][D];
__device__ float  g_sqacc[8];
__device__ int    g_pcount;
__device__ int    g_ready;
__device__ int    g_mcount;
__device__ int    g_tile = NCTA;        // dynamic tile counter (reset each run)
__device__ float  g_sq[N];
__device__ float  g_c2;                 // log2(e)/(16*bw)
__device__ uint4  g_xh[N * D * 2 / 16]; // fp16 x, row stride 384B, 16B-group XOR swizzle

// ---------------- helpers ----------------
__device__ __forceinline__ uint32_t smem_u32(const void* p) {
    uint32_t a;
    asm("{ .reg .u64 t; cvta.to.shared.u64 t, %1; cvt.u32.u64 %0, t; }" : "=r"(a) : "l"(p));
    return a;
}
#define MBAR_INIT(a, c) asm volatile("mbarrier.init.shared.b64 [%0], %1;" :: "r"(a), "r"(c) : "memory")
#define MBAR_EXPECT_TX(a, b) asm volatile("mbarrier.arrive.expect_tx.shared.b64 _, [%0], %1;" :: "r"(a), "r"(b) : "memory")
#define MBAR_WAIT(a, ph) do { \
    uint32_t _m = (a), _p = (ph), _d; \
    asm volatile("{ .reg .pred p; mbarrier.try_wait.parity.acquire.cta.shared::cta.b64 p, [%1], %2; selp.b32 %0,1,0,p; }" \
        : "=r"(_d) : "r"(_m), "r"(_p) : "memory"); \
    if (!_d) { asm volatile("{ .reg .pred P1; WL_%=: mbarrier.try_wait.parity.acquire.cta.shared::cta.b64 P1, [%0], %1, 0x989680; @P1 bra.uni WD_%=; bra.uni WL_%=; WD_%=: }" \
        :: "r"(_m), "r"(_p) : "memory"); } } while (0)
__device__ __forceinline__ void bulk_g2s(uint32_t dst, const void* src, uint32_t bytes, uint32_t mbar) {
    asm volatile("cp.async.bulk.shared::cluster.global.mbarrier::complete_tx::bytes [%0], [%1], %2, [%3];"
        :: "r"(dst), "l"(src), "r"(bytes), "r"(mbar) : "memory");
}
#define LDSM_X4(r0, r1, r2, r3, a) \
    asm volatile("ldmatrix.sync.aligned.m8n8.x4.shared.b16 {%0,%1,%2,%3}, [%4];" \
        : "=r"(r0), "=r"(r1), "=r"(r2), "=r"(r3) : "r"(a))
#define MMA16816H(d, a, b0, b1) \
    asm volatile("mma.sync.aligned.m16n8k16.row.col.f16.f16.f16.f16 " \
        "{%0,%1},{%2,%3,%4,%5},{%6,%7},{%0,%1};" \
        : "+r"((d)[0]), "+r"((d)[1]) \
        : "r"((a)[0]), "r"((a)[1]), "r"((a)[2]), "r"((a)[3]), "r"(b0), "r"(b1))
__device__ __forceinline__ float ex2f(float x) {
    float r; asm("ex2.approx.ftz.f32 %0, %1;" : "=f"(r) : "f"(x)); return r;
}

// triangular decode: tile t -> (bi, bj), bj >= bi
__device__ __forceinline__ void tdecode(int t, int& bi, int& bj) {
    float s = (2.0f * NB + 1.0f);
    int r = (int)((s - sqrtf(s * s - 8.0f * (float)t)) * 0.5f);
    if (r < 0) r = 0;
    if (r > NB - 1) r = NB - 1;
    while (r > 0 && r * NB - r * (r - 1) / 2 > t) r--;
    while ((r + 1) * NB - (r + 1) * r / 2 <= t) r++;
    bi = r;
    bj = r + (t - (r * NB - r * (r - 1) / 2));
}

// one k-step for a 32-row half (2 fm sub-blocks): 4 LDSM + 8 MMA
#define KSTEP(ACC, FOFF, KG) do { \
    uint32_t _a0[4], _a1[4], _b0[4], _b1[4]; \
    uint32_t _ga = (((uint32_t)(2*(KG)) + ahi) ^ swz) << 4; \
    uint32_t _gb = (((uint32_t)(2*(KG)) + bhi) ^ swz) << 4; \
    LDSM_X4(_a0[0],_a0[1],_a0[2],_a0[3], baseA + (FOFF) + _ga); \
    LDSM_X4(_a1[0],_a1[1],_a1[2],_a1[3], baseA + (FOFF) + 6144u + _ga); \
    LDSM_X4(_b0[0],_b0[1],_b0[2],_b0[3], baseB + _gb); \
    LDSM_X4(_b1[0],_b1[1],_b1[2],_b1[3], baseB + 6144u + _gb); \
    MMA16816H((ACC)[0][0], _a0, _b0[0], _b0[1]); \
    MMA16816H((ACC)[0][1], _a0, _b0[2], _b0[3]); \
    MMA16816H((ACC)[0][2], _a0, _b1[0], _b1[1]); \
    MMA16816H((ACC)[0][3], _a0, _b1[2], _b1[3]); \
    MMA16816H((ACC)[1][0], _a1, _b0[0], _b0[1]); \
    MMA16816H((ACC)[1][1], _a1, _b0[2], _b0[3]); \
    MMA16816H((ACC)[1][2], _a1, _b1[0], _b1[1]); \
    MMA16816H((ACC)[1][3], _a1, _b1[2], _b1[3]); \
} while (0)

// epilogue of one acc pair (4 elements) into parity buckets ta0/ta1
#define EPI1(LO, HI, NI0, NI1, NJ0, NJ1) do { \
    float2 _p0 = __half22float2(*(half2*)&(LO)); \
    float2 _p1 = __half22float2(*(half2*)&(HI)); \
    float _t, _t2, _t4, _t8; \
    _t = ex2f(fmaf(_p0.x, tc2, (NI0)+(NJ0))); _t2=_t*_t; _t4=_t2*_t2; _t8=_t4*_t4; \
    ta0 += (fmaf(_t,_t,_t) + fmaf(_t4,_t4,_t4)) + _t8*_t8; \
    _t = ex2f(fmaf(_p0.y, tc2, (NI0)+(NJ1))); _t2=_t*_t; _t4=_t2*_t2; _t8=_t4*_t4; \
    ta1 += (fmaf(_t,_t,_t) + fmaf(_t4,_t4,_t4)) + _t8*_t8; \
    _t = ex2f(fmaf(_p1.x, tc2, (NI1)+(NJ0))); _t2=_t*_t; _t4=_t2*_t2; _t8=_t4*_t4; \
    ta0 += (fmaf(_t,_t,_t) + fmaf(_t4,_t4,_t4)) + _t8*_t8; \
    _t = ex2f(fmaf(_p1.y, tc2, (NI1)+(NJ1))); _t2=_t*_t; _t4=_t2*_t2; _t8=_t4*_t4; \
    ta1 += (fmaf(_t,_t,_t) + fmaf(_t4,_t4,_t4)) + _t8*_t8; \
} while (0)

// ---------------- fused persistent kernel ----------------
#define OFF_A    0
#define OFF_B    49152
#define OFF_MBAR 98304
#define OFF_RED  98320
#define SMEM_DYN (98304 + 64 + 1024)

__global__ __launch_bounds__(256, 2) void k_all(const float* __restrict__ x,
                                                float* __restrict__ out) {
    extern __shared__ char dsm[];
    uint32_t sb = (smem_u32(dsm) + 1023u) & ~1023u;
    char* sp = dsm + (sb - smem_u32(dsm));

    int tid  = threadIdx.x;
    int wid  = tid >> 5, lane = tid & 31;
    int wM   = wid >> 2, wN = wid & 3;
    int gID  = lane >> 2, tig = lane & 3;
    int c    = blockIdx.x;

    __shared__ int s_go, s_win;
    __shared__ int s_next[2];

    // ================= phase 1: convert + reductions (CTAs 0..255) =================
    if (c < CHUNKS) {
        float* s_stage = (float*)sp;
        float* s_sq    = (float*)(sp + 24576);
        float* s_rowsq = (float*)(sp + 27648);

        #pragma unroll
        for (int it = 0; it < 3; it++) {
            int idx = tid + it * 256;
            int r = idx / 24, g = idx % 24;
            int gr = c * 32 + r;
            const float* src = x + (size_t)gr * D + g * 8;
            float4 f0 = *(const float4*)src;
            float4 f1 = *(const float4*)(src + 4);

            half2 hh[4];
            hh[0] = __float22half2_rn(make_float2(f0.x, f0.y));
            hh[1] = __float22half2_rn(make_float2(f0.z, f0.w));
            hh[2] = __float22half2_rn(make_float2(f1.x, f1.y));
            hh[3] = __float22half2_rn(make_float2(f1.z, f1.w));
            *(uint4*)((char*)g_xh + (size_t)gr * 384 +
                      (((uint32_t)g ^ (uint32_t)(gr & 7)) << 4)) = *(uint4*)hh;

            s_sq[r * 24 + g] = f0.x * f0.x + f0.y * f0.y + f0.z * f0.z + f0.w * f0.w
                             + f1.x * f1.x + f1.y * f1.y + f1.z * f1.z + f1.w * f1.w;
            float* sxp = &s_stage[r * D + g * 8];
            sxp[0] = f0.x; sxp[1] = f0.y; sxp[2] = f0.z; sxp[3] = f0.w;
            sxp[4] = f1.x; sxp[5] = f1.y; sxp[6] = f1.z; sxp[7] = f1.w;
        }
        __syncthreads();

        if (tid < 32) {
            float v = 0.f;
            #pragma unroll
            for (int k = 0; k < 24; k++) v += s_sq[tid * 24 + k];
            g_sq[c * 32 + tid] = v;
            s_rowsq[tid] = v;
        }
        if (tid >= 64) {
            int col = tid - 64;
            float cs = 0.f;
            #pragma unroll
            for (int r = 0; r < 32; r++) cs += s_stage[r * D + col];
            atomicAdd(&g_colacc[c & 7][col], cs);
        }
        __syncthreads();
        if (tid == 0) {
            float tot = 0.f;
            #pragma unroll
            for (int r = 0; r < 32; r++) tot += s_rowsq[r];
            atomicAdd(&g_sqacc[c & 7], tot);
        }
    }

    // ================= grid barrier + bandwidth constant =================
    __threadfence();
    __syncthreads();
    if (tid == 0) s_go = (atomicAdd(&g_pcount, 1) == NCTA - 1) ? 1 : 0;
    __syncthreads();
    if (s_go) {
        __threadfence();
        float* s_red2 = (float*)sp;
        float cs = 0.f;
        if (tid < D) {
            #pragma unroll
            for (int r = 0; r < 8; r++) cs += __ldcg(&g_colacc[r][tid]);
        }
        s_red2[tid] = cs * cs;
        __syncthreads();
        #pragma unroll
        for (int o = 128; o >= 32; o >>= 1) {
            if (tid < o) s_red2[tid] += s_red2[tid + o];
            __syncthreads();
        }
        if (tid < 32) {
            float v = s_red2[tid];
            #pragma unroll
            for (int o = 16; o > 0; o >>= 1) v += __shfl_down_sync(0xffffffffu, v, o);
            if (tid == 0) {
                float sumsq = 0.f;
                #pragma unroll
                for (int r = 0; r < 8; r++) sumsq += __ldcg(&g_sqacc[r]);
                double sumL2 = 2.0 * (double)N * (double)sumsq - 2.0 * (double)v;
                double bw = sumL2 / ((double)N * (double)N - (double)N);
                bw *= 0.25;
                g_c2 = (float)(1.4426950408889634 / (bw * 16.0));
                g_loss = 0.0;
                __threadfence();
                atomicExch(&g_ready, 1);
            }
        }
    }
    if (tid == 0) {
        volatile int* rp = &g_ready;
        while (*rp == 0) {}
    }
    __syncthreads();
    __threadfence();

    // ================= phase 2: dynamic schedule + interleaved HMMA tiles ==========
    int t = c;                    // first tile = own block id (g_tile starts at NCTA)
    int bi, bj;
    tdecode(t, bi, bj);

    uint32_t mbar = sb + OFF_MBAR;
    if (tid == 0) MBAR_INIT(mbar, 1);
    __syncthreads();
    if (tid == 0) {
        MBAR_EXPECT_TX(mbar, 2 * TILE_BYTES);
        const char* xh = (const char*)g_xh;
        bulk_g2s(sb + OFF_A, xh + (size_t)bi * TILE_BYTES, TILE_BYTES, mbar);
        bulk_g2s(sb + OFF_B, xh + (size_t)bj * TILE_BYTES, TILE_BYTES, mbar);
    }

    uint32_t swz   = (uint32_t)(lane & 7);
    uint32_t ahi   = (uint32_t)(lane >> 4);
    uint32_t bhi   = (uint32_t)((lane >> 3) & 1);
    uint32_t baseA = sb + OFF_A + (uint32_t)(wM * 64 + (lane & 15)) * 384u;
    uint32_t baseB = sb + OFF_B + (uint32_t)(wN * 32 + ((lane >> 4) << 3) + (lane & 7)) * 384u;

    float c2 = __ldcg(&g_c2), tc2 = 2.f * c2, nc2 = -c2;

    float master = 0.f;
    int phase = 0;
    int it = 0;

    while (t < NTILES) {
        // grab next tile early (ATOMG latency hides under mbar wait + MMA)
        if (tid == 0) s_next[it & 1] = atomicAdd(&g_tile, 1);

        bool diag = (bi == bj);
        float nsi[8], nsj[8];
        #pragma unroll
        for (int fm = 0; fm < 4; fm++) {
            nsi[fm * 2]     = nc2 * __ldg(&g_sq[bi * BM + wM * 64 + fm * 16 + gID]);
            nsi[fm * 2 + 1] = nc2 * __ldg(&g_sq[bi * BM + wM * 64 + fm * 16 + gID + 8]);
        }
        #pragma unroll
        for (int fn = 0; fn < 4; fn++) {
            nsj[fn * 2]     = nc2 * __ldg(&g_sq[bj * BM + wN * 32 + fn * 8 + tig * 2]);
            nsj[fn * 2 + 1] = nc2 * __ldg(&g_sq[bj * BM + wN * 32 + fn * 8 + tig * 2 + 1]);
        }

        MBAR_WAIT(mbar, phase);
        phase ^= 1;

        float ta0 = 0.f, ta1 = 0.f;
        uint32_t acc0[2][4][2], acc1[2][4][2];
        #pragma unroll
        for (int a = 0; a < 2; a++)
            #pragma unroll
            for (int b = 0; b < 4; b++) {
                acc0[a][b][0] = 0u; acc0[a][b][1] = 0u;
                acc1[a][b][0] = 0u; acc1[a][b][1] = 0u;
            }

        // ---- half 0 (rows 0..31 of warp tile): full k sweep ----
        KSTEP(acc0, 0u, 0);  KSTEP(acc0, 0u, 1);  KSTEP(acc0, 0u, 2);
        KSTEP(acc0, 0u, 3);  KSTEP(acc0, 0u, 4);  KSTEP(acc0, 0u, 5);
        KSTEP(acc0, 0u, 6);  KSTEP(acc0, 0u, 7);  KSTEP(acc0, 0u, 8);
        KSTEP(acc0, 0u, 9);  KSTEP(acc0, 0u, 10); KSTEP(acc0, 0u, 11);

        // ---- half 1 MMA with half-0 epilogue interleaved (independent ops) ----
        KSTEP(acc1, 12288u, 0);  KSTEP(acc1, 12288u, 1);  KSTEP(acc1, 12288u, 2);
        EPI1(acc0[0][0][0], acc0[0][0][1], nsi[0], nsi[1], nsj[0], nsj[1]);
        EPI1(acc0[0][1][0], acc0[0][1][1], nsi[0], nsi[1], nsj[2], nsj[3]);
        KSTEP(acc1, 12288u, 3);  KSTEP(acc1, 12288u, 4);  KSTEP(acc1, 12288u, 5);
        EPI1(acc0[0][2][0], acc0[0][2][1], nsi[0], nsi[1], nsj[4], nsj[5]);
        EPI1(acc0[0][3][0], acc0[0][3][1], nsi[0], nsi[1], nsj[6], nsj[7]);
        KSTEP(acc1, 12288u, 6);  KSTEP(acc1, 12288u, 7);  KSTEP(acc1, 12288u, 8);
        EPI1(acc0[1][0][0], acc0[1][0][1], nsi[2], nsi[3], nsj[0], nsj[1]);
        EPI1(acc0[1][1][0], acc0[1][1][1], nsi[2], nsi[3], nsj[2], nsj[3]);
        KSTEP(acc1, 12288u, 9);  KSTEP(acc1, 12288u, 10); KSTEP(acc1, 12288u, 11);
        EPI1(acc0[1][2][0], acc0[1][2][1], nsi[2], nsi[3], nsj[4], nsj[5]);
        EPI1(acc0[1][3][0], acc0[1][3][1], nsi[2], nsi[3], nsj[6], nsj[7]);

        __syncthreads();   // smem reads done (and s_next visible) -> safe to overwrite

        int nt = s_next[it & 1];
        int nbi = 0, nbj = 0;
        if (nt < NTILES) {
            tdecode(nt, nbi, nbj);
            if (tid == 0) {
                MBAR_EXPECT_TX(mbar, 2 * TILE_BYTES);
                const char* xh = (const char*)g_xh;
                bulk_g2s(sb + OFF_A, xh + (size_t)nbi * TILE_BYTES, TILE_BYTES, mbar);
                bulk_g2s(sb + OFF_B, xh + (size_t)nbj * TILE_BYTES, TILE_BYTES, mbar);
            }
        }

        // ---- half 1 epilogue (overlaps async prefetch) ----
        EPI1(acc1[0][0][0], acc1[0][0][1], nsi[4], nsi[5], nsj[0], nsj[1]);
        EPI1(acc1[0][1][0], acc1[0][1][1], nsi[4], nsi[5], nsj[2], nsj[3]);
        EPI1(acc1[0][2][0], acc1[0][2][1], nsi[4], nsi[5], nsj[4], nsj[5]);
        EPI1(acc1[0][3][0], acc1[0][3][1], nsi[4], nsi[5], nsj[6], nsj[7]);
        EPI1(acc1[1][0][0], acc1[1][0][1], nsi[6], nsi[7], nsj[0], nsj[1]);
        EPI1(acc1[1][1][0], acc1[1][1][1], nsi[6], nsi[7], nsj[2], nsj[3]);
        EPI1(acc1[1][2][0], acc1[1][2][1], nsi[6], nsi[7], nsj[4], nsj[5]);
        EPI1(acc1[1][3][0], acc1[1][3][1], nsi[6], nsi[7], nsj[6], nsj[7]);

        // diag tiles self-count both orderings (+own diagonal -> replaces +5N), weight 1
        float tp = (gID & 1) ? (ta1 - ta0) : (ta0 - ta1);
        master += diag ? tp : 2.f * tp;

        t = nt; bi = nbi; bj = nbj;
        it++;
    }

    float part = master;
    #pragma unroll
    for (int o = 16; o > 0; o >>= 1) part += __shfl_xor_sync(0xffffffffu, part, o);
    float* s_red = (float*)(sp + OFF_RED);
    if (lane == 0) s_red[wid] = part;
    __syncthreads();
    if (tid == 0) {
        float v = 0.f;
        #pragma unroll
        for (int w = 0; w < 8; w++) v += s_red[w];
        atomicAdd(&g_loss, (double)v);
    }

    // ================= finalization by last CTA (parallel state reset) =================
    __threadfence();
    __syncthreads();
    if (tid == 0) s_win = (atomicAdd(&g_mcount, 1) == NCTA - 1) ? 1 : 0;
    __syncthreads();
    if (s_win) {
        __threadfence();
        if (tid < D) {
            #pragma unroll
            for (int r = 0; r < 8; r++) g_colacc[r][tid] = 0.f;
        }
        if (tid < 8) g_sqacc[tid] = 0.f;
        __syncthreads();
        if (tid == 0) {
            double hn = (double)(N / 2);
            out[0] = (float)(g_loss / (hn * hn));   // diag tiles already include ~5N
            g_pcount = 0;
            g_ready  = 0;
            g_mcount = 0;
            g_tile   = NCTA;
        }
    }
}

// ---------------- launch ----------------
extern "C" void kernel_launch(void* const* d_in, const int* in_sizes, int n_in,
                              void* d_out, int out_size) {
    const float* x = (const float*)d_in[0];
    float* out = (float*)d_out;

    cudaFuncSetAttribute(k_all, cudaFuncAttributeMaxDynamicSharedMemorySize, SMEM_DYN);
    k_all<<<NCTA, 256, SMEM_DYN>>>(x, out);
}